// round 1
// baseline (speedup 1.0000x reference)
#include <cuda_runtime.h>

// VectorQuantizer: x[8,128,128,64] f32, W[1024,64] f32.
// out = concat(quantized_with_grad (== quantized), quantized, indices-as-f32)
//
// argmin_k ||f - w_k||^2  ==  argmax_k ( f.w_k - 0.5*||w_k||^2 )

#define NROWS   (8 * 128 * 128)   // 131072
#define DIM     64
#define NCODE   1024
#define KC      256               // codewords per smem tile
#define THREADS 256

__device__ float g_wsqhalf[NCODE];

// --- kernel 1: 0.5 * ||w_k||^2 per codeword -------------------------------
__global__ void wsq_kernel(const float* __restrict__ W) {
    int k = blockIdx.x * blockDim.x + threadIdx.x;
    if (k >= NCODE) return;
    const float4* w = reinterpret_cast<const float4*>(W + (size_t)k * DIM);
    float s = 0.0f;
#pragma unroll
    for (int i = 0; i < DIM / 4; i++) {
        float4 v = w[i];
        s += v.x * v.x + v.y * v.y + v.z * v.z + v.w * v.w;
    }
    g_wsqhalf[k] = 0.5f * s;
}

// --- kernel 2: per-row argmax over codebook -------------------------------
__global__ __launch_bounds__(THREADS, 2)
void vq_kernel(const float* __restrict__ x,
               const float* __restrict__ W,
               float* __restrict__ out) {
    __shared__ float4 sW[KC * (DIM / 4)];   // 64 KB
    __shared__ float  sB[KC];               // 1 KB

    const int row = blockIdx.x * THREADS + threadIdx.x;   // grid sized exactly

    // Load this row's vector into 32 packed f32x2 registers.
    unsigned long long f[DIM / 2];
    {
        const float4* xr = reinterpret_cast<const float4*>(x + (size_t)row * DIM);
#pragma unroll
        for (int i = 0; i < DIM / 4; i++) {
            float4 v = xr[i];
            asm("mov.b64 %0, {%1, %2};" : "=l"(f[2 * i + 0]) : "f"(v.x), "f"(v.y));
            asm("mov.b64 %0, {%1, %2};" : "=l"(f[2 * i + 1]) : "f"(v.z), "f"(v.w));
        }
    }

    float best  = -3.0e38f;
    int   bestk = 0;

    for (int kt = 0; kt < NCODE; kt += KC) {
        __syncthreads();
        // Cooperative tile load: 256 codewords * 16 float4 = 4096 float4.
        {
            const float4* wt = reinterpret_cast<const float4*>(W + (size_t)kt * DIM);
            for (int i = threadIdx.x; i < KC * (DIM / 4); i += THREADS)
                sW[i] = wt[i];
            for (int i = threadIdx.x; i < KC; i += THREADS)
                sB[i] = g_wsqhalf[kt + i];
        }
        __syncthreads();

#pragma unroll 2
        for (int kc = 0; kc < KC; kc++) {
            const float4* wrow = &sW[kc * (DIM / 4)];
            // Two independent packed accumulator chains.
            unsigned long long acc0 = 0ULL, acc1 = 0ULL;  // packed {0.f,0.f}
#pragma unroll
            for (int i = 0; i < DIM / 4; i++) {
                float4 wv = wrow[i];   // warp-uniform broadcast LDS.128
                unsigned long long w0, w1;
                asm("mov.b64 %0, {%1, %2};" : "=l"(w0) : "f"(wv.x), "f"(wv.y));
                asm("mov.b64 %0, {%1, %2};" : "=l"(w1) : "f"(wv.z), "f"(wv.w));
                asm("fma.rn.f32x2 %0, %1, %2, %0;" : "+l"(acc0) : "l"(f[2 * i + 0]), "l"(w0));
                asm("fma.rn.f32x2 %0, %1, %2, %0;" : "+l"(acc1) : "l"(f[2 * i + 1]), "l"(w1));
            }
            float a, b, c, d;
            asm("mov.b64 {%0, %1}, %2;" : "=f"(a), "=f"(b) : "l"(acc0));
            asm("mov.b64 {%0, %1}, %2;" : "=f"(c), "=f"(d) : "l"(acc1));
            float score = ((a + b) + (c + d)) - sB[kc];
            if (score > best) { best = score; bestk = kt + kc; }
        }
    }

    // Epilogue: gather W[bestk] (L2-resident) and write both copies + index.
    {
        const float4* wb = reinterpret_cast<const float4*>(W + (size_t)bestk * DIM);
        float4* o1 = reinterpret_cast<float4*>(out + (size_t)row * DIM);
        float4* o2 = reinterpret_cast<float4*>(out + ((size_t)NROWS + row) * DIM);
#pragma unroll
        for (int i = 0; i < DIM / 4; i++) {
            float4 v = wb[i];
            o1[i] = v;
            o2[i] = v;
        }
        out[(size_t)2 * NROWS * DIM + row] = (float)bestk;
    }
}

// --- launch ---------------------------------------------------------------
extern "C" void kernel_launch(void* const* d_in, const int* in_sizes, int n_in,
                              void* d_out, int out_size) {
    const float* x = (const float*)d_in[0];   // [131072, 64]
    const float* W = (const float*)d_in[1];   // [1024, 64]
    float* out = (float*)d_out;

    wsq_kernel<<<(NCODE + 255) / 256, 256>>>(W);
    vq_kernel<<<NROWS / THREADS, THREADS>>>(x, W, out);
}

// round 4
// speedup vs baseline: 1.9321x; 1.9321x over previous
#include <cuda_runtime.h>
#include <cuda_bf16.h>
#include <cstdint>

// VectorQuantizer: x[131072,64] f32, W[1024,64] f32.
// out = [quantized(N,64) | quantized(N,64) | indices-as-f32(N)]
// argmin_k ||f-w_k||^2 == argmax_k ( f.w_k - 0.5||w_k||^2 )
// Scores via mma.sync bf16 with exact 3-way split (hh,hm,mh,hl,lh,mm).

#define NROWS   131072
#define DIM     64
#define NCODE   1024
#define MCTA    128
#define NCHUNK  64
#define NCHUNKS (NCODE / NCHUNK)
#define THREADS 256

#define ROWB    144                    // padded row stride bytes (72 bf16)
#define SPLIT_A (MCTA * ROWB)          // 18432
#define SPLIT_B (NCHUNK * ROWB)        // 9216
#define SM_A    0
#define SM_B    (3 * SPLIT_A)          // 55296
#define SM_BIAS (SM_B + 3 * SPLIT_B)   // 82944
#define SMEM_TOTAL (SM_BIAS + 256)     // 83200
// merge buffers reuse [0, 8KB) of the A region after the chunk loop

__device__ __align__(16) __nv_bfloat16 g_Wsplit[3][NCODE][DIM];
__device__ float g_bias[NCODE];

// ---- helpers ---------------------------------------------------------------
__device__ __forceinline__ uint32_t smem_to_u32(const void* p) {
    uint32_t a;
    asm("{ .reg .u64 t; cvta.to.shared.u64 t, %1; cvt.u32.u64 %0, t; }" : "=r"(a) : "l"(p));
    return a;
}
__device__ __forceinline__ void split3(float v, __nv_bfloat16& h, __nv_bfloat16& m, __nv_bfloat16& l) {
    h = __float2bfloat16_rn(v);
    float r1 = v - __bfloat162float(h);
    m = __float2bfloat16_rn(r1);
    float r2 = r1 - __bfloat162float(m);
    l = __float2bfloat16_rn(r2);
}
__device__ __forceinline__ uint32_t pack2(__nv_bfloat16 a, __nv_bfloat16 b) {
    __nv_bfloat162 t = __halves2bfloat162(a, b);
    return *reinterpret_cast<uint32_t*>(&t);
}
#define LDSM_X4(r0, r1, r2, r3, a) \
    asm volatile("ldmatrix.sync.aligned.m8n8.x4.shared.b16 {%0,%1,%2,%3}, [%4];" \
                 : "=r"(r0), "=r"(r1), "=r"(r2), "=r"(r3) : "r"(a))
#define LDSM_X2(r0, r1, a) \
    asm volatile("ldmatrix.sync.aligned.m8n8.x2.shared.b16 {%0,%1}, [%2];" \
                 : "=r"(r0), "=r"(r1) : "r"(a))
#define MMA_BF16(d, a, b) \
    asm volatile("mma.sync.aligned.m16n8k16.row.col.f32.bf16.bf16.f32 " \
                 "{%0,%1,%2,%3}, {%4,%5,%6,%7}, {%8,%9}, {%0,%1,%2,%3};" \
                 : "+f"((d)[0]), "+f"((d)[1]), "+f"((d)[2]), "+f"((d)[3]) \
                 : "r"((a)[0]), "r"((a)[1]), "r"((a)[2]), "r"((a)[3]), "r"((b)[0]), "r"((b)[1]))

// ---- prep: split codebook + bias -------------------------------------------
__global__ void prep_kernel(const float* __restrict__ W) {
    int k = blockIdx.x * blockDim.x + threadIdx.x;
    if (k >= NCODE) return;
    float s = 0.0f;
#pragma unroll
    for (int d = 0; d < DIM; d++) {
        float v = W[(size_t)k * DIM + d];
        __nv_bfloat16 h, m, l;
        split3(v, h, m, l);
        g_Wsplit[0][k][d] = h; g_Wsplit[1][k][d] = m; g_Wsplit[2][k][d] = l;
        s = fmaf(v, v, s);
    }
    g_bias[k] = -0.5f * s;
}

// ---- main kernel ------------------------------------------------------------
__global__ __launch_bounds__(THREADS, 2)
void vq_kernel(const float* __restrict__ x,
               const float* __restrict__ W,
               float* __restrict__ out) {
    extern __shared__ char smem[];
    const uint32_t sbase = smem_to_u32(smem);
    const int tid  = threadIdx.x;
    const int lane = tid & 31;
    const int wid  = tid >> 5;
    const int wm   = (wid >> 1) * 32;   // warp M base (rows): pair shares it
    const int wn   = (wid & 1)  * 32;   // warp N base (codes within chunk)

    // ---- stage A: load x rows, 3-way split, padded smem -----
    {
        const int row = tid >> 1, half = tid & 1;
        const float4* xr = reinterpret_cast<const float4*>(
            x + ((size_t)blockIdx.x * MCTA + row) * DIM + half * 32);
        char* a0 = smem + SM_A + row * ROWB + half * 64;
#pragma unroll
        for (int i = 0; i < 8; i++) {
            float4 v = xr[i];
            __nv_bfloat16 h0, m0, l0, h1, m1, l1, h2, m2, l2, h3, m3, l3;
            split3(v.x, h0, m0, l0); split3(v.y, h1, m1, l1);
            split3(v.z, h2, m2, l2); split3(v.w, h3, m3, l3);
            *reinterpret_cast<uint32_t*>(a0 + 0 * SPLIT_A + i * 8)     = pack2(h0, h1);
            *reinterpret_cast<uint32_t*>(a0 + 0 * SPLIT_A + i * 8 + 4) = pack2(h2, h3);
            *reinterpret_cast<uint32_t*>(a0 + 1 * SPLIT_A + i * 8)     = pack2(m0, m1);
            *reinterpret_cast<uint32_t*>(a0 + 1 * SPLIT_A + i * 8 + 4) = pack2(m2, m3);
            *reinterpret_cast<uint32_t*>(a0 + 2 * SPLIT_A + i * 8)     = pack2(l0, l1);
            *reinterpret_cast<uint32_t*>(a0 + 2 * SPLIT_A + i * 8 + 4) = pack2(l2, l3);
        }
    }

    // ldmatrix address bases
    const int l4 = lane & 15;
    const uint32_t aBase = sbase + SM_A + (uint32_t)(wm + l4) * ROWB + (lane >> 4) * 16;
    const uint32_t bBase = sbase + SM_B + (uint32_t)(wn + (l4 & 7)) * ROWB + (l4 >> 3) * 16;

    float best[4] = {-3.0e38f, -3.0e38f, -3.0e38f, -3.0e38f};
    int   bidx[4] = {0, 0, 0, 0};

    const uint4* gW = reinterpret_cast<const uint4*>(g_Wsplit);
    const float* sBias = reinterpret_cast<const float*>(smem + SM_BIAS);

    for (int c = 0; c < NCHUNKS; c++) {
        __syncthreads();   // previous chunk's reads done before overwrite
        // load B chunk: 3 splits x 64 codes x 64 bf16
        for (int i = tid; i < 3 * NCHUNK * 8; i += THREADS) {
            int split = i >> 9, rem = i & 511, n = rem >> 3, ch = rem & 7;
            uint4 v = gW[((size_t)split * NCODE + c * NCHUNK + n) * 8 + ch];
            *reinterpret_cast<uint4*>(smem + SM_B + split * SPLIT_B + n * ROWB + ch * 16) = v;
        }
        if (tid < NCHUNK)
            *reinterpret_cast<float*>(smem + SM_BIAS + tid * 4) = g_bias[c * NCHUNK + tid];
        __syncthreads();

        // init accumulators with bias
        float acc[2][4][4];
#pragma unroll
        for (int nt = 0; nt < 4; nt++) {
            float b0 = sBias[wn + nt * 8 + (lane & 3) * 2];
            float b1 = sBias[wn + nt * 8 + (lane & 3) * 2 + 1];
#pragma unroll
            for (int m = 0; m < 2; m++) {
                acc[m][nt][0] = b0; acc[m][nt][1] = b1;
                acc[m][nt][2] = b0; acc[m][nt][3] = b1;
            }
        }

#pragma unroll
        for (int k = 0; k < 4; k++) {
            uint32_t A[3][2][4];
#pragma unroll
            for (int sa = 0; sa < 3; sa++)
#pragma unroll
                for (int m = 0; m < 2; m++) {
                    uint32_t a = aBase + sa * SPLIT_A + m * 16 * ROWB + k * 32;
                    LDSM_X4(A[sa][m][0], A[sa][m][1], A[sa][m][2], A[sa][m][3], a);
                }
#pragma unroll
            for (int sb = 0; sb < 3; sb++) {
#pragma unroll
                for (int nt = 0; nt < 4; nt++) {
                    uint32_t B[2];
                    uint32_t b = bBase + sb * SPLIT_B + nt * 8 * ROWB + k * 32;
                    LDSM_X2(B[0], B[1], b);
#pragma unroll
                    for (int sa = 0; sa + sb < 3; sa++) {
                        MMA_BF16(acc[0][nt], A[sa][0], B);
                        MMA_BF16(acc[1][nt], A[sa][1], B);
                    }
                }
            }
        }

        // per-chunk argmax update (4 independent row-chains per thread)
#pragma unroll
        for (int m = 0; m < 2; m++)
#pragma unroll
            for (int h = 0; h < 2; h++) {
                const int q = m * 2 + h;
#pragma unroll
                for (int nt = 0; nt < 4; nt++)
#pragma unroll
                    for (int e = 0; e < 2; e++) {
                        float v = acc[m][nt][h * 2 + e];
                        int n = c * NCHUNK + wn + nt * 8 + (lane & 3) * 2 + e;
                        if (v > best[q]) { best[q] = v; bidx[q] = n; }
                    }
            }
    }

    // ---- reduce across the 4 lanes sharing each row --------
#pragma unroll
    for (int q = 0; q < 4; q++) {
#pragma unroll
        for (int off = 1; off < 4; off <<= 1) {
            float ov = __shfl_xor_sync(0xFFFFFFFFu, best[q], off);
            int   oi = __shfl_xor_sync(0xFFFFFFFFu, bidx[q], off);
            if (ov > best[q] || (ov == best[q] && oi < bidx[q])) {
                best[q] = ov; bidx[q] = oi;
            }
        }
    }

    // ---- cross-warp merge: warps wid and wid^1 cover the SAME rows but
    // complementary code halves (wn 0 vs 32). Merge via smem, even warp wins.
    {
        __syncthreads();   // all warps done reading A/B smem
        float* mb = reinterpret_cast<float*>(smem);            // [8][32][4] best
        int*   mi = reinterpret_cast<int*>(smem + 4096);       // [8][32][4] idx
        const int off = (wid * 32 + lane) * 4;
#pragma unroll
        for (int q = 0; q < 4; q++) { mb[off + q] = best[q]; mi[off + q] = bidx[q]; }
        __syncthreads();
        if ((wid & 1) == 0) {
            const int poff = ((wid ^ 1) * 32 + lane) * 4;
#pragma unroll
            for (int q = 0; q < 4; q++) {
                float pv = mb[poff + q];
                int   pi = mi[poff + q];
                if (pv > best[q] || (pv == best[q] && pi < bidx[q])) {
                    best[q] = pv; bidx[q] = pi;
                }
            }
        }
    }

    // ---- gather codewords + write outputs (even warps only) ----
    if ((wid & 1) == 0) {
        const int lq = lane & 3;    // dim slice: lq*16 .. lq*16+15
#pragma unroll
        for (int q = 0; q < 4; q++) {
            const int r = wm + (lane >> 2) + (q & 1) * 8 + (q >> 1) * 16;
            const size_t grow = (size_t)blockIdx.x * MCTA + r;
            const int K = bidx[q];
            const float4* wsrc = reinterpret_cast<const float4*>(W + (size_t)K * DIM + lq * 16);
            float4* o1 = reinterpret_cast<float4*>(out + grow * DIM + lq * 16);
            float4* o2 = reinterpret_cast<float4*>(out + ((size_t)NROWS + grow) * DIM + lq * 16);
#pragma unroll
            for (int i = 0; i < 4; i++) {
                float4 v = wsrc[i];
                o1[i] = v;
                o2[i] = v;
            }
            if (lq == 0)
                out[(size_t)2 * NROWS * DIM + grow] = (float)K;
        }
    }
}

// ---- launch -----------------------------------------------------------------
extern "C" void kernel_launch(void* const* d_in, const int* in_sizes, int n_in,
                              void* d_out, int out_size) {
    const float* x = (const float*)d_in[0];
    const float* W = (const float*)d_in[1];
    float* out = (float*)d_out;

    cudaFuncSetAttribute(vq_kernel, cudaFuncAttributeMaxDynamicSharedMemorySize, SMEM_TOTAL);
    prep_kernel<<<NCODE / 256, 256>>>(W);
    vq_kernel<<<NROWS / MCTA, THREADS, SMEM_TOTAL>>>(x, W, out);
}

// round 5
// speedup vs baseline: 2.2197x; 1.1488x over previous
#include <cuda_runtime.h>
#include <cuda_bf16.h>
#include <cstdint>

// VectorQuantizer: x[131072,64] f32, W[1024,64] f32.
// out = [quantized(N,64) | quantized(N,64) | indices-as-f32(N)]
// argmin_k ||f-w_k||^2 == argmax_k ( f.w_k - 0.5||w_k||^2 )
// mma.sync bf16, exact 3-way split, 6 product passes (hh,hm,mh,hl,lh,mm).
// R5: A frags persistent in registers, cp.async double-buffered B, x4 B-LDSM.

#define NROWS   131072
#define DIM     64
#define NCODE   1024
#define MCTA    128
#define NCHUNK  64
#define NCHUNKS (NCODE / NCHUNK)
#define THREADS 256

#define ROWB    144                     // padded row stride (72 bf16)
#define SPLIT_A (MCTA * ROWB)           // 18432
#define SPLIT_B (NCHUNK * ROWB)         // 9216
#define BUF_B   (3 * SPLIT_B)           // 27648
#define SM_A    0
#define SM_B    (3 * SPLIT_A)           // 55296
#define SM_BIAS (SM_B + 2 * BUF_B)      // 110592
#define SMEM_TOTAL (SM_BIAS + 512)      // 111104

__device__ __align__(16) __nv_bfloat16 g_Wsplit[3][NCODE][DIM];
__device__ __align__(16) float g_bias[NCODE];

// ---- helpers ---------------------------------------------------------------
__device__ __forceinline__ uint32_t smem_to_u32(const void* p) {
    uint32_t a;
    asm("{ .reg .u64 t; cvta.to.shared.u64 t, %1; cvt.u32.u64 %0, t; }" : "=r"(a) : "l"(p));
    return a;
}
__device__ __forceinline__ void split3(float v, __nv_bfloat16& h, __nv_bfloat16& m, __nv_bfloat16& l) {
    h = __float2bfloat16_rn(v);
    float r1 = v - __bfloat162float(h);
    m = __float2bfloat16_rn(r1);
    float r2 = r1 - __bfloat162float(m);
    l = __float2bfloat16_rn(r2);
}
__device__ __forceinline__ uint32_t pack2(__nv_bfloat16 a, __nv_bfloat16 b) {
    __nv_bfloat162 t = __halves2bfloat162(a, b);
    return *reinterpret_cast<uint32_t*>(&t);
}
#define LDSM_X4(r0, r1, r2, r3, a) \
    asm volatile("ldmatrix.sync.aligned.m8n8.x4.shared.b16 {%0,%1,%2,%3}, [%4];" \
                 : "=r"(r0), "=r"(r1), "=r"(r2), "=r"(r3) : "r"(a))
#define MMA_BF16(d, a, b) \
    asm volatile("mma.sync.aligned.m16n8k16.row.col.f32.bf16.bf16.f32 " \
                 "{%0,%1,%2,%3}, {%4,%5,%6,%7}, {%8,%9}, {%0,%1,%2,%3};" \
                 : "+f"((d)[0]), "+f"((d)[1]), "+f"((d)[2]), "+f"((d)[3]) \
                 : "r"((a)[0]), "r"((a)[1]), "r"((a)[2]), "r"((a)[3]), "r"((b)[0]), "r"((b)[1]))
#define CP_ASYNC16(dst, src) \
    asm volatile("cp.async.cg.shared.global [%0], [%1], 16;" \
                 :: "r"((uint32_t)(dst)), "l"((size_t)__cvta_generic_to_global(src)) : "memory")
#define CP_COMMIT() asm volatile("cp.async.commit_group;" ::: "memory")
#define CP_WAIT(n)  asm volatile("cp.async.wait_group %0;" :: "n"(n) : "memory")

// ---- prep: split codebook + bias -------------------------------------------
__global__ void prep_kernel(const float* __restrict__ W) {
    int k = blockIdx.x * blockDim.x + threadIdx.x;
    if (k >= NCODE) return;
    float s = 0.0f;
#pragma unroll
    for (int d = 0; d < DIM; d++) {
        float v = W[(size_t)k * DIM + d];
        __nv_bfloat16 h, m, l;
        split3(v, h, m, l);
        g_Wsplit[0][k][d] = h; g_Wsplit[1][k][d] = m; g_Wsplit[2][k][d] = l;
        s = fmaf(v, v, s);
    }
    g_bias[k] = -0.5f * s;
}

// issue cp.async for B chunk `kbase` into buffer bsel
__device__ __forceinline__ void prefetch_chunk(uint32_t sbase, int bsel, int kbase, int tid) {
    const char* gw = reinterpret_cast<const char*>(g_Wsplit);
#pragma unroll
    for (int t = 0; t < 6; t++) {
        int i = tid + t * THREADS;                 // 0..1535
        int split = i >> 9, rem = i & 511, n = rem >> 3, ch = rem & 7;
        uint32_t dst = sbase + SM_B + bsel * BUF_B + split * SPLIT_B + n * ROWB + ch * 16;
        const char* src = gw + (((size_t)split * NCODE + kbase + n) * 8 + ch) * 16;
        CP_ASYNC16(dst, src);
    }
    if (tid < 16)
        CP_ASYNC16(sbase + SM_BIAS + bsel * 256 + tid * 16,
                   reinterpret_cast<const char*>(g_bias) + (size_t)kbase * 4 + tid * 16);
    CP_COMMIT();
}

// ---- main kernel ------------------------------------------------------------
__global__ __launch_bounds__(THREADS, 2)
void vq_kernel(const float* __restrict__ x,
               const float* __restrict__ W,
               float* __restrict__ out) {
    extern __shared__ char smem[];
    const uint32_t sbase = smem_to_u32(smem);
    const int tid  = threadIdx.x;
    const int lane = tid & 31;
    const int wid  = tid >> 5;
    const int wm   = wid * 16;          // 16 rows per warp, all 64 codes/chunk

    // kick off chunk 0 load before anything else
    prefetch_chunk(sbase, 0, 0, tid);

    // ---- stage A rows into smem (3-way split) -------------
    {
        const int row = tid >> 1, half = tid & 1;
        const float4* xr = reinterpret_cast<const float4*>(
            x + ((size_t)blockIdx.x * MCTA + row) * DIM + half * 32);
        char* a0 = smem + SM_A + row * ROWB + half * 64;
#pragma unroll
        for (int i = 0; i < 8; i++) {
            float4 v = xr[i];
            __nv_bfloat16 h0, m0, l0, h1, m1, l1, h2, m2, l2, h3, m3, l3;
            split3(v.x, h0, m0, l0); split3(v.y, h1, m1, l1);
            split3(v.z, h2, m2, l2); split3(v.w, h3, m3, l3);
            *reinterpret_cast<uint32_t*>(a0 + 0 * SPLIT_A + i * 8)     = pack2(h0, h1);
            *reinterpret_cast<uint32_t*>(a0 + 0 * SPLIT_A + i * 8 + 4) = pack2(h2, h3);
            *reinterpret_cast<uint32_t*>(a0 + 1 * SPLIT_A + i * 8)     = pack2(m0, m1);
            *reinterpret_cast<uint32_t*>(a0 + 1 * SPLIT_A + i * 8 + 4) = pack2(m2, m3);
            *reinterpret_cast<uint32_t*>(a0 + 2 * SPLIT_A + i * 8)     = pack2(l0, l1);
            *reinterpret_cast<uint32_t*>(a0 + 2 * SPLIT_A + i * 8 + 4) = pack2(l2, l3);
        }
    }
    __syncthreads();

    // ---- A fragments -> registers, persistent for all chunks ----
    uint32_t Af[3][4][4];
    {
        const uint32_t aB = sbase + SM_A + (uint32_t)(wm + (lane & 15)) * ROWB + (lane >> 4) * 16;
#pragma unroll
        for (int sa = 0; sa < 3; sa++)
#pragma unroll
            for (int k = 0; k < 4; k++)
                LDSM_X4(Af[sa][k][0], Af[sa][k][1], Af[sa][k][2], Af[sa][k][3],
                        aB + sa * SPLIT_A + k * 32);
    }

    float best[2] = {-3.0e38f, -3.0e38f};
    int   bidx[2] = {0, 0};

    // B ldmatrix base: x4 covers two n-tiles (codes n0..n0+7 and n0+8..n0+15)
    const uint32_t bb = sbase + SM_B
        + (uint32_t)(((lane >> 4) & 1) * 8 + (lane & 7)) * ROWB
        + ((lane >> 3) & 1) * 16;

    for (int c = 0; c < NCHUNKS; c++) {
        if (c + 1 < NCHUNKS) {
            prefetch_chunk(sbase, (c + 1) & 1, (c + 1) * NCHUNK, tid);
            CP_WAIT(1);
        } else {
            CP_WAIT(0);
        }
        __syncthreads();

        const float* sBias = reinterpret_cast<const float*>(smem + SM_BIAS + (c & 1) * 256);
        float acc[8][4];
#pragma unroll
        for (int nt = 0; nt < 8; nt++) {
            float b0 = sBias[nt * 8 + (lane & 3) * 2];
            float b1 = sBias[nt * 8 + (lane & 3) * 2 + 1];
            acc[nt][0] = b0; acc[nt][1] = b1; acc[nt][2] = b0; acc[nt][3] = b1;
        }

        const uint32_t bbc = bb + (c & 1) * BUF_B;
#pragma unroll
        for (int k = 0; k < 4; k++) {
#pragma unroll
            for (int sb = 0; sb < 3; sb++) {
#pragma unroll
                for (int ntp = 0; ntp < 4; ntp++) {
                    uint32_t Bf[4];
                    LDSM_X4(Bf[0], Bf[1], Bf[2], Bf[3],
                            bbc + sb * SPLIT_B + ntp * 16 * ROWB + k * 32);
#pragma unroll
                    for (int sa = 0; sa < 3 - sb; sa++) {
                        MMA_BF16(acc[2 * ntp],     Af[sa][k], Bf);
                        MMA_BF16(acc[2 * ntp + 1], Af[sa][k], Bf + 2);
                    }
                }
            }
        }

        // argmax update: 2 row-chains per thread (rows lane>>2 and +8)
#pragma unroll
        for (int nt = 0; nt < 8; nt++)
#pragma unroll
            for (int q = 0; q < 2; q++)
#pragma unroll
                for (int e = 0; e < 2; e++) {
                    float v = acc[nt][q * 2 + e];
                    int n = c * NCHUNK + nt * 8 + (lane & 3) * 2 + e;
                    if (v > best[q]) { best[q] = v; bidx[q] = n; }
                }

        __syncthreads();   // buf (c&1) free for the c+2 prefetch
    }

    // ---- reduce across the 4 lanes sharing each row (cols) ----
#pragma unroll
    for (int q = 0; q < 2; q++) {
#pragma unroll
        for (int off = 1; off < 4; off <<= 1) {
            float ov = __shfl_xor_sync(0xFFFFFFFFu, best[q], off);
            int   oi = __shfl_xor_sync(0xFFFFFFFFu, bidx[q], off);
            if (ov > best[q] || (ov == best[q] && oi < bidx[q])) {
                best[q] = ov; bidx[q] = oi;
            }
        }
    }

    // ---- gather codewords + write outputs ----
    const int lq = lane & 3;   // dim slice lq*16 .. lq*16+15
#pragma unroll
    for (int q = 0; q < 2; q++) {
        const int r = wm + (lane >> 2) + q * 8;
        const size_t grow = (size_t)blockIdx.x * MCTA + r;
        const int K = bidx[q];
        const float4* wsrc = reinterpret_cast<const float4*>(W + (size_t)K * DIM + lq * 16);
        float4* o1 = reinterpret_cast<float4*>(out + grow * DIM + lq * 16);
        float4* o2 = reinterpret_cast<float4*>(out + ((size_t)NROWS + grow) * DIM + lq * 16);
#pragma unroll
        for (int i = 0; i < 4; i++) {
            float4 v = wsrc[i];
            o1[i] = v;
            o2[i] = v;
        }
        if (lq == 0)
            out[(size_t)2 * NROWS * DIM + grow] = (float)K;
    }
}

// ---- launch -----------------------------------------------------------------
extern "C" void kernel_launch(void* const* d_in, const int* in_sizes, int n_in,
                              void* d_out, int out_size) {
    const float* x = (const float*)d_in[0];
    const float* W = (const float*)d_in[1];
    float* out = (float*)d_out;

    cudaFuncSetAttribute(vq_kernel, cudaFuncAttributeMaxDynamicSharedMemorySize, SMEM_TOTAL);
    prep_kernel<<<NCODE / 256, 256>>>(W);
    vq_kernel<<<NROWS / MCTA, THREADS, SMEM_TOTAL>>>(x, W, out);
}

// round 6
// speedup vs baseline: 2.2213x; 1.0007x over previous
#include <cuda_runtime.h>
#include <cuda_bf16.h>
#include <cstdint>

// VectorQuantizer: x[131072,64] f32, W[1024,64] f32.
// out = [quantized(N,64) | quantized(N,64) | indices-as-f32(N)]
// argmin_k ||f-w_k||^2 == argmax_k ( f.w_k - 0.5||w_k||^2 )
// mma.sync bf16, exact 3-way split, 6 product passes (hh,hm,mh,hl,lh,mm).
// R6: paired-ntile MMA scheduling (dep distance 2 -> 4) to close tensor idle.

#define NROWS   131072
#define DIM     64
#define NCODE   1024
#define MCTA    128
#define NCHUNK  64
#define NCHUNKS (NCODE / NCHUNK)
#define THREADS 256

#define ROWB    144                     // padded row stride (72 bf16)
#define SPLIT_A (MCTA * ROWB)           // 18432
#define SPLIT_B (NCHUNK * ROWB)         // 9216
#define BUF_B   (3 * SPLIT_B)           // 27648
#define SM_A    0
#define SM_B    (3 * SPLIT_A)           // 55296
#define SM_BIAS (SM_B + 2 * BUF_B)      // 110592
#define SMEM_TOTAL (SM_BIAS + 512)      // 111104

__device__ __align__(16) __nv_bfloat16 g_Wsplit[3][NCODE][DIM];
__device__ __align__(16) float g_bias[NCODE];

// ---- helpers ---------------------------------------------------------------
__device__ __forceinline__ uint32_t smem_to_u32(const void* p) {
    uint32_t a;
    asm("{ .reg .u64 t; cvta.to.shared.u64 t, %1; cvt.u32.u64 %0, t; }" : "=r"(a) : "l"(p));
    return a;
}
__device__ __forceinline__ void split3(float v, __nv_bfloat16& h, __nv_bfloat16& m, __nv_bfloat16& l) {
    h = __float2bfloat16_rn(v);
    float r1 = v - __bfloat162float(h);
    m = __float2bfloat16_rn(r1);
    float r2 = r1 - __bfloat162float(m);
    l = __float2bfloat16_rn(r2);
}
__device__ __forceinline__ uint32_t pack2(__nv_bfloat16 a, __nv_bfloat16 b) {
    __nv_bfloat162 t = __halves2bfloat162(a, b);
    return *reinterpret_cast<uint32_t*>(&t);
}
#define LDSM_X4(r0, r1, r2, r3, a) \
    asm volatile("ldmatrix.sync.aligned.m8n8.x4.shared.b16 {%0,%1,%2,%3}, [%4];" \
                 : "=r"(r0), "=r"(r1), "=r"(r2), "=r"(r3) : "r"(a))
#define MMA_BF16(d, a, b) \
    asm volatile("mma.sync.aligned.m16n8k16.row.col.f32.bf16.bf16.f32 " \
                 "{%0,%1,%2,%3}, {%4,%5,%6,%7}, {%8,%9}, {%0,%1,%2,%3};" \
                 : "+f"((d)[0]), "+f"((d)[1]), "+f"((d)[2]), "+f"((d)[3]) \
                 : "r"((a)[0]), "r"((a)[1]), "r"((a)[2]), "r"((a)[3]), "r"((b)[0]), "r"((b)[1]))
#define CP_ASYNC16(dst, src) \
    asm volatile("cp.async.cg.shared.global [%0], [%1], 16;" \
                 :: "r"((uint32_t)(dst)), "l"((size_t)__cvta_generic_to_global(src)) : "memory")
#define CP_COMMIT() asm volatile("cp.async.commit_group;" ::: "memory")
#define CP_WAIT(n)  asm volatile("cp.async.wait_group %0;" :: "n"(n) : "memory")

// ---- prep: split codebook + bias -------------------------------------------
__global__ void prep_kernel(const float* __restrict__ W) {
    int k = blockIdx.x * blockDim.x + threadIdx.x;
    if (k >= NCODE) return;
    float s = 0.0f;
#pragma unroll
    for (int d = 0; d < DIM; d++) {
        float v = W[(size_t)k * DIM + d];
        __nv_bfloat16 h, m, l;
        split3(v, h, m, l);
        g_Wsplit[0][k][d] = h; g_Wsplit[1][k][d] = m; g_Wsplit[2][k][d] = l;
        s = fmaf(v, v, s);
    }
    g_bias[k] = -0.5f * s;
}

// issue cp.async for B chunk `kbase` into buffer bsel
__device__ __forceinline__ void prefetch_chunk(uint32_t sbase, int bsel, int kbase, int tid) {
    const char* gw = reinterpret_cast<const char*>(g_Wsplit);
#pragma unroll
    for (int t = 0; t < 6; t++) {
        int i = tid + t * THREADS;                 // 0..1535
        int split = i >> 9, rem = i & 511, n = rem >> 3, ch = rem & 7;
        uint32_t dst = sbase + SM_B + bsel * BUF_B + split * SPLIT_B + n * ROWB + ch * 16;
        const char* src = gw + (((size_t)split * NCODE + kbase + n) * 8 + ch) * 16;
        CP_ASYNC16(dst, src);
    }
    if (tid < 16)
        CP_ASYNC16(sbase + SM_BIAS + bsel * 256 + tid * 16,
                   reinterpret_cast<const char*>(g_bias) + (size_t)kbase * 4 + tid * 16);
    CP_COMMIT();
}

// ---- main kernel ------------------------------------------------------------
__global__ __launch_bounds__(THREADS, 2)
void vq_kernel(const float* __restrict__ x,
               const float* __restrict__ W,
               float* __restrict__ out) {
    extern __shared__ char smem[];
    const uint32_t sbase = smem_to_u32(smem);
    const int tid  = threadIdx.x;
    const int lane = tid & 31;
    const int wid  = tid >> 5;
    const int wm   = wid * 16;          // 16 rows per warp, all 64 codes/chunk

    // kick off chunk 0 load before anything else
    prefetch_chunk(sbase, 0, 0, tid);

    // ---- stage A rows into smem (3-way split) -------------
    {
        const int row = tid >> 1, half = tid & 1;
        const float4* xr = reinterpret_cast<const float4*>(
            x + ((size_t)blockIdx.x * MCTA + row) * DIM + half * 32);
        char* a0 = smem + SM_A + row * ROWB + half * 64;
#pragma unroll
        for (int i = 0; i < 8; i++) {
            float4 v = xr[i];
            __nv_bfloat16 h0, m0, l0, h1, m1, l1, h2, m2, l2, h3, m3, l3;
            split3(v.x, h0, m0, l0); split3(v.y, h1, m1, l1);
            split3(v.z, h2, m2, l2); split3(v.w, h3, m3, l3);
            *reinterpret_cast<uint32_t*>(a0 + 0 * SPLIT_A + i * 8)     = pack2(h0, h1);
            *reinterpret_cast<uint32_t*>(a0 + 0 * SPLIT_A + i * 8 + 4) = pack2(h2, h3);
            *reinterpret_cast<uint32_t*>(a0 + 1 * SPLIT_A + i * 8)     = pack2(m0, m1);
            *reinterpret_cast<uint32_t*>(a0 + 1 * SPLIT_A + i * 8 + 4) = pack2(m2, m3);
            *reinterpret_cast<uint32_t*>(a0 + 2 * SPLIT_A + i * 8)     = pack2(l0, l1);
            *reinterpret_cast<uint32_t*>(a0 + 2 * SPLIT_A + i * 8 + 4) = pack2(l2, l3);
        }
    }
    __syncthreads();

    // ---- A fragments -> registers, persistent for all chunks ----
    uint32_t Af[3][4][4];
    {
        const uint32_t aB = sbase + SM_A + (uint32_t)(wm + (lane & 15)) * ROWB + (lane >> 4) * 16;
#pragma unroll
        for (int sa = 0; sa < 3; sa++)
#pragma unroll
            for (int k = 0; k < 4; k++)
                LDSM_X4(Af[sa][k][0], Af[sa][k][1], Af[sa][k][2], Af[sa][k][3],
                        aB + sa * SPLIT_A + k * 32);
    }

    float best[2] = {-3.0e38f, -3.0e38f};
    int   bidx[2] = {0, 0};

    // B ldmatrix base: x4 covers two n-tiles (codes n0..n0+7 and n0+8..n0+15)
    const uint32_t bb = sbase + SM_B
        + (uint32_t)(((lane >> 4) & 1) * 8 + (lane & 7)) * ROWB
        + ((lane >> 3) & 1) * 16;

    for (int c = 0; c < NCHUNKS; c++) {
        if (c + 1 < NCHUNKS) {
            prefetch_chunk(sbase, (c + 1) & 1, (c + 1) * NCHUNK, tid);
            CP_WAIT(1);
        } else {
            CP_WAIT(0);
        }
        __syncthreads();

        const float* sBias = reinterpret_cast<const float*>(smem + SM_BIAS + (c & 1) * 256);
        float acc[8][4];
#pragma unroll
        for (int nt = 0; nt < 8; nt++) {
            float2 b01 = *reinterpret_cast<const float2*>(&sBias[nt * 8 + (lane & 3) * 2]);
            acc[nt][0] = b01.x; acc[nt][1] = b01.y;
            acc[nt][2] = b01.x; acc[nt][3] = b01.y;
        }

        const uint32_t bbc = bb + (c & 1) * BUF_B;
#pragma unroll
        for (int k = 0; k < 4; k++) {
#pragma unroll
            for (int sb = 0; sb < 3; sb++) {
#pragma unroll
                for (int np = 0; np < 2; np++) {   // pairs of 16-wide n-tiles
                    uint32_t Bf0[4], Bf1[4];
                    uint32_t bB = bbc + sb * SPLIT_B + np * 32 * ROWB + k * 32;
                    LDSM_X4(Bf0[0], Bf0[1], Bf0[2], Bf0[3], bB);
                    LDSM_X4(Bf1[0], Bf1[1], Bf1[2], Bf1[3], bB + 16 * ROWB);
                    // 4 independent acc chains per sa step (dep distance 4)
#pragma unroll
                    for (int sa = 0; sa < 3 - sb; sa++) {
                        MMA_BF16(acc[4 * np + 0], Af[sa][k], Bf0);
                        MMA_BF16(acc[4 * np + 1], Af[sa][k], Bf0 + 2);
                        MMA_BF16(acc[4 * np + 2], Af[sa][k], Bf1);
                        MMA_BF16(acc[4 * np + 3], Af[sa][k], Bf1 + 2);
                    }
                }
            }
        }

        // argmax update: 2 row-chains per thread (rows lane>>2 and +8)
#pragma unroll
        for (int nt = 0; nt < 8; nt++)
#pragma unroll
            for (int q = 0; q < 2; q++)
#pragma unroll
                for (int e = 0; e < 2; e++) {
                    float v = acc[nt][q * 2 + e];
                    int n = c * NCHUNK + nt * 8 + (lane & 3) * 2 + e;
                    if (v > best[q]) { best[q] = v; bidx[q] = n; }
                }

        __syncthreads();   // buf (c&1) free for the c+2 prefetch
    }

    // ---- reduce across the 4 lanes sharing each row (cols) ----
#pragma unroll
    for (int q = 0; q < 2; q++) {
#pragma unroll
        for (int off = 1; off < 4; off <<= 1) {
            float ov = __shfl_xor_sync(0xFFFFFFFFu, best[q], off);
            int   oi = __shfl_xor_sync(0xFFFFFFFFu, bidx[q], off);
            if (ov > best[q] || (ov == best[q] && oi < bidx[q])) {
                best[q] = ov; bidx[q] = oi;
            }
        }
    }

    // ---- gather codewords + write outputs ----
    const int lq = lane & 3;   // dim slice lq*16 .. lq*16+15
#pragma unroll
    for (int q = 0; q < 2; q++) {
        const int r = wm + (lane >> 2) + q * 8;
        const size_t grow = (size_t)blockIdx.x * MCTA + r;
        const int K = bidx[q];
        const float4* wsrc = reinterpret_cast<const float4*>(W + (size_t)K * DIM + lq * 16);
        float4* o1 = reinterpret_cast<float4*>(out + grow * DIM + lq * 16);
        float4* o2 = reinterpret_cast<float4*>(out + ((size_t)NROWS + grow) * DIM + lq * 16);
#pragma unroll
        for (int i = 0; i < 4; i++) {
            float4 v = wsrc[i];
            o1[i] = v;
            o2[i] = v;
        }
        if (lq == 0)
            out[(size_t)2 * NROWS * DIM + grow] = (float)K;
    }
}

// ---- launch -----------------------------------------------------------------
extern "C" void kernel_launch(void* const* d_in, const int* in_sizes, int n_in,
                              void* d_out, int out_size) {
    const float* x = (const float*)d_in[0];
    const float* W = (const float*)d_in[1];
    float* out = (float*)d_out;

    cudaFuncSetAttribute(vq_kernel, cudaFuncAttributeMaxDynamicSharedMemorySize, SMEM_TOTAL);
    prep_kernel<<<NCODE / 256, 256>>>(W);
    vq_kernel<<<NROWS / MCTA, THREADS, SMEM_TOTAL>>>(x, W, out);
}